// round 1
// baseline (speedup 1.0000x reference)
#include <cuda_runtime.h>
#include <math.h>

#define NMAX 100000
#define EMAX 3200000

// ---------- device scratch (allocation-free: __device__ globals) ----------
__device__ float g_A[(size_t)NMAX * 256];   // support buffer
__device__ float g_B[(size_t)NMAX * 256];   // hidden buffer
__device__ int   g_counts[NMAX];
__device__ int   g_tmp[NMAX];
__device__ int   g_rowptr[NMAX + 1];
__device__ int   g_cursor[NMAX];
__device__ int2  g_csr[EMAX];               // {col, float_as_int(val)}
__device__ int   g_bsum[256];
__device__ int   g_boff[256];

// ---------- CSR build ----------
__global__ void k_zero(int n) {
    int i = blockIdx.x * blockDim.x + threadIdx.x;
    if (i < n) g_counts[i] = 0;
}

__global__ void k_hist(const int* __restrict__ erow, int e) {
    int i = blockIdx.x * blockDim.x + threadIdx.x;
    if (i < e) atomicAdd(&g_counts[erow[i]], 1);
}

// per-block inclusive scan of 1024 counts
__global__ void k_scan1(int n) {
    __shared__ int sh[1024];
    int t = threadIdx.x;
    int i = blockIdx.x * 1024 + t;
    int v = (i < n) ? g_counts[i] : 0;
    sh[t] = v;
    __syncthreads();
    #pragma unroll
    for (int off = 1; off < 1024; off <<= 1) {
        int add = (t >= off) ? sh[t - off] : 0;
        __syncthreads();
        sh[t] += add;
        __syncthreads();
    }
    if (i < n) g_tmp[i] = sh[t];
    if (t == 1023) g_bsum[blockIdx.x] = sh[1023];
}

// exclusive scan of block sums (NB <= 256)
__global__ void k_scan2(int nb) {
    __shared__ int sh[256];
    int t = threadIdx.x;
    int v = (t < nb) ? g_bsum[t] : 0;
    sh[t] = v;
    __syncthreads();
    #pragma unroll
    for (int off = 1; off < 256; off <<= 1) {
        int add = (t >= off) ? sh[t - off] : 0;
        __syncthreads();
        sh[t] += add;
        __syncthreads();
    }
    if (t < nb) g_boff[t] = sh[t] - v;   // exclusive
}

__global__ void k_scan3(int n) {
    int i = blockIdx.x * blockDim.x + threadIdx.x;
    if (i < n) {
        int incl = g_tmp[i] + g_boff[i >> 10];
        g_rowptr[i + 1] = incl;
        g_cursor[i] = incl - g_counts[i];
        if (i == 0) g_rowptr[0] = 0;
    }
}

__global__ void k_scatter(const int* __restrict__ erow, const int* __restrict__ ecol,
                          const float* __restrict__ eval, int e) {
    int i = blockIdx.x * blockDim.x + threadIdx.x;
    if (i < e) {
        int r = erow[i];
        int pos = atomicAdd(&g_cursor[r], 1);
        g_csr[pos] = make_int2(ecol[i], __float_as_int(eval[i]));
    }
}

// ---------- fp32 tiled GEMM: C[M,Nc] = A[M,K] @ B[K,Nc] ----------
// BM=BN=64, BK=16, 256 threads, 4x4 microtile
__global__ void k_sgemm(const float* __restrict__ A, const float* __restrict__ B,
                        float* __restrict__ C, int M, int K, int Nc) {
    __shared__ float As[16][64];
    __shared__ float Bs[16][64];
    int tid = threadIdx.x;
    int tx = tid & 15, ty = tid >> 4;
    int rowB = blockIdx.y * 64, colB = blockIdx.x * 64;
    int aRow = tid >> 2, aK = (tid & 3) * 4;
    int bRow = tid >> 4, bCol = (tid & 15) * 4;

    float acc[4][4];
    #pragma unroll
    for (int i = 0; i < 4; i++)
        #pragma unroll
        for (int j = 0; j < 4; j++) acc[i][j] = 0.f;

    for (int k0 = 0; k0 < K; k0 += 16) {
        float4 av = make_float4(0.f, 0.f, 0.f, 0.f);
        if (rowB + aRow < M)
            av = *(const float4*)(A + (size_t)(rowB + aRow) * K + k0 + aK);
        As[aK + 0][aRow] = av.x;
        As[aK + 1][aRow] = av.y;
        As[aK + 2][aRow] = av.z;
        As[aK + 3][aRow] = av.w;
        float4 bv = *(const float4*)(B + (size_t)(k0 + bRow) * Nc + colB + bCol);
        *(float4*)&Bs[bRow][bCol] = bv;
        __syncthreads();
        #pragma unroll
        for (int k = 0; k < 16; ++k) {
            float4 a = *(const float4*)&As[k][ty * 4];
            float4 b = *(const float4*)&Bs[k][tx * 4];
            float a4[4] = {a.x, a.y, a.z, a.w};
            float b4[4] = {b.x, b.y, b.z, b.w};
            #pragma unroll
            for (int i = 0; i < 4; i++)
                #pragma unroll
                for (int j = 0; j < 4; j++)
                    acc[i][j] += a4[i] * b4[j];
        }
        __syncthreads();
    }
    #pragma unroll
    for (int i = 0; i < 4; i++) {
        int r = rowB + ty * 4 + i;
        if (r < M)
            *(float4*)(C + (size_t)r * Nc + colB + tx * 4) =
                make_float4(acc[i][0], acc[i][1], acc[i][2], acc[i][3]);
    }
}

// ---------- SpMM F=256, warp-per-row, fused bias (+ReLU) ----------
__global__ void k_spmm256(const float* __restrict__ sup, const float* __restrict__ bias,
                          float* __restrict__ out, int relu, int n) {
    int w = (blockIdx.x * blockDim.x + threadIdx.x) >> 5;
    int lane = threadIdx.x & 31;
    if (w >= n) return;
    int s = g_rowptr[w], e = g_rowptr[w + 1];
    float4 a0 = make_float4(0.f, 0.f, 0.f, 0.f);
    float4 a1 = a0;

    int i = s;
    for (; i + 1 < e; i += 2) {
        int2 p0 = __ldg(&g_csr[i]);
        int2 p1 = __ldg(&g_csr[i + 1]);
        float v0 = __int_as_float(p0.y);
        float v1 = __int_as_float(p1.y);
        const float4* s0 = (const float4*)(sup + (size_t)p0.x * 256);
        const float4* s1 = (const float4*)(sup + (size_t)p1.x * 256);
        float4 x0 = __ldg(&s0[lane]);
        float4 x1 = __ldg(&s0[lane + 32]);
        float4 y0 = __ldg(&s1[lane]);
        float4 y1 = __ldg(&s1[lane + 32]);
        a0.x += v0 * x0.x; a0.y += v0 * x0.y; a0.z += v0 * x0.z; a0.w += v0 * x0.w;
        a1.x += v0 * x1.x; a1.y += v0 * x1.y; a1.z += v0 * x1.z; a1.w += v0 * x1.w;
        a0.x += v1 * y0.x; a0.y += v1 * y0.y; a0.z += v1 * y0.z; a0.w += v1 * y0.w;
        a1.x += v1 * y1.x; a1.y += v1 * y1.y; a1.z += v1 * y1.z; a1.w += v1 * y1.w;
    }
    if (i < e) {
        int2 p0 = __ldg(&g_csr[i]);
        float v0 = __int_as_float(p0.y);
        const float4* s0 = (const float4*)(sup + (size_t)p0.x * 256);
        float4 x0 = __ldg(&s0[lane]);
        float4 x1 = __ldg(&s0[lane + 32]);
        a0.x += v0 * x0.x; a0.y += v0 * x0.y; a0.z += v0 * x0.z; a0.w += v0 * x0.w;
        a1.x += v0 * x1.x; a1.y += v0 * x1.y; a1.z += v0 * x1.z; a1.w += v0 * x1.w;
    }

    float4 b0 = __ldg(&((const float4*)bias)[lane]);
    float4 b1 = __ldg(&((const float4*)bias)[lane + 32]);
    a0.x += b0.x; a0.y += b0.y; a0.z += b0.z; a0.w += b0.w;
    a1.x += b1.x; a1.y += b1.y; a1.z += b1.z; a1.w += b1.w;
    if (relu) {
        a0.x = fmaxf(a0.x, 0.f); a0.y = fmaxf(a0.y, 0.f);
        a0.z = fmaxf(a0.z, 0.f); a0.w = fmaxf(a0.w, 0.f);
        a1.x = fmaxf(a1.x, 0.f); a1.y = fmaxf(a1.y, 0.f);
        a1.z = fmaxf(a1.z, 0.f); a1.w = fmaxf(a1.w, 0.f);
    }
    float4* op = (float4*)(out + (size_t)w * 256);
    op[lane] = a0;
    op[lane + 32] = a1;
}

// ---------- SpMM F=64, warp-per-row, fused bias ----------
__global__ void k_spmm64(const float* __restrict__ sup, const float* __restrict__ bias,
                         float* __restrict__ out, int n) {
    int w = (blockIdx.x * blockDim.x + threadIdx.x) >> 5;
    int lane = threadIdx.x & 31;
    if (w >= n) return;
    int s = g_rowptr[w], e = g_rowptr[w + 1];
    float2 a = make_float2(0.f, 0.f);

    int i = s;
    for (; i + 1 < e; i += 2) {
        int2 p0 = __ldg(&g_csr[i]);
        int2 p1 = __ldg(&g_csr[i + 1]);
        float v0 = __int_as_float(p0.y);
        float v1 = __int_as_float(p1.y);
        float2 x0 = __ldg(&((const float2*)(sup + (size_t)p0.x * 64))[lane]);
        float2 x1 = __ldg(&((const float2*)(sup + (size_t)p1.x * 64))[lane]);
        a.x += v0 * x0.x; a.y += v0 * x0.y;
        a.x += v1 * x1.x; a.y += v1 * x1.y;
    }
    if (i < e) {
        int2 p0 = __ldg(&g_csr[i]);
        float v0 = __int_as_float(p0.y);
        float2 x0 = __ldg(&((const float2*)(sup + (size_t)p0.x * 64))[lane]);
        a.x += v0 * x0.x; a.y += v0 * x0.y;
    }

    float2 b = __ldg(&((const float2*)bias)[lane]);
    a.x += b.x; a.y += b.y;
    ((float2*)(out + (size_t)w * 64))[lane] = a;
}

// ---------- log_softmax over 64 logits per row ----------
__global__ void k_lsm64(float* __restrict__ out, int n) {
    int w = (blockIdx.x * blockDim.x + threadIdx.x) >> 5;
    int lane = threadIdx.x & 31;
    if (w >= n) return;
    float2* p = (float2*)(out + (size_t)w * 64);
    float2 v = p[lane];
    float m = fmaxf(v.x, v.y);
    #pragma unroll
    for (int o = 16; o; o >>= 1) m = fmaxf(m, __shfl_xor_sync(0xffffffffu, m, o));
    float s = expf(v.x - m) + expf(v.y - m);
    #pragma unroll
    for (int o = 16; o; o >>= 1) s += __shfl_xor_sync(0xffffffffu, s, o);
    float l = m + logf(s);
    p[lane] = make_float2(v.x - l, v.y - l);
}

// ---------- launch ----------
extern "C" void kernel_launch(void* const* d_in, const int* in_sizes, int n_in,
                              void* d_out, int out_size) {
    const float* x    = (const float*)d_in[0];
    const int*   erow = (const int*)d_in[1];
    const int*   ecol = (const int*)d_in[2];
    const float* eval = (const float*)d_in[3];
    const float* W1   = (const float*)d_in[4];
    const float* b1   = (const float*)d_in[5];
    const float* W2   = (const float*)d_in[6];
    const float* b2   = (const float*)d_in[7];
    const float* W3   = (const float*)d_in[8];
    const float* b3   = (const float*)d_in[9];

    int N = in_sizes[0] / 512;
    int E = in_sizes[1];

    float *pA, *pB;
    cudaGetSymbolAddress((void**)&pA, g_A);
    cudaGetSymbolAddress((void**)&pB, g_B);

    // --- CSR build ---
    k_zero<<<(N + 255) / 256, 256>>>(N);
    k_hist<<<(E + 255) / 256, 256>>>(erow, E);
    int NB = (N + 1023) / 1024;
    k_scan1<<<NB, 1024>>>(N);
    k_scan2<<<1, 256>>>(NB);
    k_scan3<<<(N + 255) / 256, 256>>>(N);
    k_scatter<<<(E + 255) / 256, 256>>>(erow, ecol, eval, E);

    int warpBlocks = (N * 32 + 255) / 256;
    dim3 gBig(256 / 64, (N + 63) / 64);
    dim3 gOut(64 / 64, (N + 63) / 64);

    // layer 1: A = x@W1 ; B = relu(spmm(A) + b1)
    k_sgemm<<<gBig, 256>>>(x, W1, pA, N, 512, 256);
    k_spmm256<<<warpBlocks, 256>>>(pA, b1, pB, 1, N);

    // layer 2: A = B@W2 ; B = relu(spmm(A) + b2)
    k_sgemm<<<gBig, 256>>>(pB, W2, pA, N, 256, 256);
    k_spmm256<<<warpBlocks, 256>>>(pA, b2, pB, 1, N);

    // layer 3: A = B@W3 ; out = spmm(A) + b3 ; log_softmax
    k_sgemm<<<gOut, 256>>>(pB, W3, pA, N, 256, 64);
    k_spmm64<<<warpBlocks, 256>>>(pA, b3, (float*)d_out, N);
    k_lsm64<<<warpBlocks, 256>>>((float*)d_out, N);
}

// round 3
// speedup vs baseline: 1.5567x; 1.5567x over previous
#include <cuda_runtime.h>
#include <math.h>
#include <stdint.h>

#define NMAX 100000
#define EMAX 3200000

// ---------- device scratch (allocation-free: __device__ globals) ----------
__device__ __align__(256) float g_A[(size_t)NMAX * 256];   // buffer A
__device__ __align__(256) float g_B[(size_t)NMAX * 256];   // buffer B
__device__ __align__(256) float g_W1T[256 * 512];
__device__ __align__(256) float g_W2T[256 * 256];
__device__ __align__(256) float g_W3T[64 * 256];
__device__ int   g_counts[NMAX];
__device__ int   g_tmp[NMAX];
__device__ int   g_rowptr[NMAX + 1];
__device__ int   g_cursor[NMAX];
__device__ int2  g_csr[EMAX];               // {col, float_as_int(val)}
__device__ int   g_bsum[256];
__device__ int   g_boff[256];

// ---------- CSR build ----------
__global__ void k_zero(int n) {
    int i = blockIdx.x * blockDim.x + threadIdx.x;
    if (i < n) g_counts[i] = 0;
}
__global__ void k_hist(const int* __restrict__ erow, int e) {
    int i = blockIdx.x * blockDim.x + threadIdx.x;
    if (i < e) atomicAdd(&g_counts[erow[i]], 1);
}
__global__ void k_scan1(int n) {
    __shared__ int sh[1024];
    int t = threadIdx.x;
    int i = blockIdx.x * 1024 + t;
    int v = (i < n) ? g_counts[i] : 0;
    sh[t] = v;
    __syncthreads();
    #pragma unroll
    for (int off = 1; off < 1024; off <<= 1) {
        int add = (t >= off) ? sh[t - off] : 0;
        __syncthreads();
        sh[t] += add;
        __syncthreads();
    }
    if (i < n) g_tmp[i] = sh[t];
    if (t == 1023) g_bsum[blockIdx.x] = sh[1023];
}
__global__ void k_scan2(int nb) {
    __shared__ int sh[256];
    int t = threadIdx.x;
    int v = (t < nb) ? g_bsum[t] : 0;
    sh[t] = v;
    __syncthreads();
    #pragma unroll
    for (int off = 1; off < 256; off <<= 1) {
        int add = (t >= off) ? sh[t - off] : 0;
        __syncthreads();
        sh[t] += add;
        __syncthreads();
    }
    if (t < nb) g_boff[t] = sh[t] - v;
}
__global__ void k_scan3(int n) {
    int i = blockIdx.x * blockDim.x + threadIdx.x;
    if (i < n) {
        int incl = g_tmp[i] + g_boff[i >> 10];
        g_rowptr[i + 1] = incl;
        g_cursor[i] = incl - g_counts[i];
        if (i == 0) g_rowptr[0] = 0;
    }
}
__global__ void k_scatter(const int* __restrict__ erow, const int* __restrict__ ecol,
                          const float* __restrict__ eval, int e) {
    int i = blockIdx.x * blockDim.x + threadIdx.x;
    if (i < e) {
        int r = erow[i];
        int pos = atomicAdd(&g_cursor[r], 1);
        g_csr[pos] = make_int2(ecol[i], __float_as_int(eval[i]));
    }
}

// ---------- small transpose: WT[n*K+k] = W[k*N+n] ----------
__global__ void k_transpose(const float* __restrict__ W, float* __restrict__ WT, int K, int N) {
    int i = blockIdx.x * blockDim.x + threadIdx.x;
    if (i < K * N) {
        int k = i / N, n = i % N;
        WT[(size_t)n * K + k] = W[i];
    }
}

// ---------- TF32 mma.sync GEMM: C[M,N] = A[M,K] @ BT[N,K]^T ----------
// block tile 128x64, 256 threads (8 warps as 4m x 2n), warp tile 32x32,
// k staged in chunks of 32. smem stride 36 floats -> conflict-free frag loads.
__device__ __forceinline__ uint32_t f2tf32(float f) {
    uint32_t r;
    asm("cvt.rna.tf32.f32 %0, %1;" : "=r"(r) : "f"(f));
    return r;
}

__global__ void __launch_bounds__(256, 2)
k_gemm_mma(const float* __restrict__ A, const float* __restrict__ BT,
           float* __restrict__ C, int M, int K, int N) {
    __shared__ uint32_t As[128][36];
    __shared__ uint32_t Bs[64][36];

    int tid = threadIdx.x;
    int w = tid >> 5, lane = tid & 31;
    int gid = lane >> 2, tig = lane & 3;
    int warp_m = w >> 1, warp_n = w & 1;
    int m0w = warp_m * 32, n0w = warp_n * 32;
    int tileRow = blockIdx.y * 128;
    int tileCol = blockIdx.x * 64;

    float acc[2][4][4];
    #pragma unroll
    for (int mt = 0; mt < 2; mt++)
        #pragma unroll
        for (int nt = 0; nt < 4; nt++)
            #pragma unroll
            for (int q = 0; q < 4; q++) acc[mt][nt][q] = 0.f;

    // gmem->smem load indices
    int arow = tid >> 1;               // 0..127
    int aq0  = (tid & 1) * 4;          // 0 or 4 (quad offset, 4 quads each)
    int brow = tid >> 2;               // 0..63
    int bq0  = tid & 3;                // quads bq0 and bq0+4

    for (int k0 = 0; k0 < K; k0 += 32) {
        // A tile: 128 rows x 32 k
        {
            int gr = tileRow + arow;
            const float* src = A + (size_t)gr * K + k0;
            #pragma unroll
            for (int q = 0; q < 4; q++) {
                float4 v = make_float4(0.f, 0.f, 0.f, 0.f);
                if (gr < M) v = *(const float4*)(src + (aq0 + q) * 4);
                int kk = (aq0 + q) * 4;
                As[arow][kk + 0] = f2tf32(v.x);
                As[arow][kk + 1] = f2tf32(v.y);
                As[arow][kk + 2] = f2tf32(v.z);
                As[arow][kk + 3] = f2tf32(v.w);
            }
        }
        // B tile: 64 n-rows x 32 k   (BT is [N][K] row-major)
        {
            const float* src = BT + (size_t)(tileCol + brow) * K + k0;
            #pragma unroll
            for (int qi = 0; qi < 2; qi++) {
                int q = bq0 + qi * 4;
                float4 v = *(const float4*)(src + q * 4);
                int kk = q * 4;
                Bs[brow][kk + 0] = f2tf32(v.x);
                Bs[brow][kk + 1] = f2tf32(v.y);
                Bs[brow][kk + 2] = f2tf32(v.z);
                Bs[brow][kk + 3] = f2tf32(v.w);
            }
        }
        __syncthreads();

        #pragma unroll
        for (int ks = 0; ks < 4; ks++) {
            int kk = ks * 8;
            uint32_t af[2][4], bf[4][2];
            #pragma unroll
            for (int mt = 0; mt < 2; mt++) {
                int m = m0w + mt * 16 + gid;
                af[mt][0] = As[m][kk + tig];
                af[mt][1] = As[m + 8][kk + tig];
                af[mt][2] = As[m][kk + tig + 4];
                af[mt][3] = As[m + 8][kk + tig + 4];
            }
            #pragma unroll
            for (int nt = 0; nt < 4; nt++) {
                int n = n0w + nt * 8 + gid;
                bf[nt][0] = Bs[n][kk + tig];
                bf[nt][1] = Bs[n][kk + tig + 4];
            }
            #pragma unroll
            for (int mt = 0; mt < 2; mt++)
                #pragma unroll
                for (int nt = 0; nt < 4; nt++) {
                    asm volatile(
                        "mma.sync.aligned.m16n8k8.row.col.f32.tf32.tf32.f32 "
                        "{%0,%1,%2,%3}, {%4,%5,%6,%7}, {%8,%9}, {%0,%1,%2,%3};"
                        : "+f"(acc[mt][nt][0]), "+f"(acc[mt][nt][1]),
                          "+f"(acc[mt][nt][2]), "+f"(acc[mt][nt][3])
                        : "r"(af[mt][0]), "r"(af[mt][1]), "r"(af[mt][2]), "r"(af[mt][3]),
                          "r"(bf[nt][0]), "r"(bf[nt][1]));
                }
        }
        __syncthreads();
    }

    // epilogue: scattered float2 stores
    #pragma unroll
    for (int mt = 0; mt < 2; mt++) {
        int r0 = tileRow + m0w + mt * 16 + gid;
        int r1 = r0 + 8;
        #pragma unroll
        for (int nt = 0; nt < 4; nt++) {
            int c = tileCol + n0w + nt * 8 + tig * 2;
            if (r0 < M)
                *(float2*)(C + (size_t)r0 * N + c) = make_float2(acc[mt][nt][0], acc[mt][nt][1]);
            if (r1 < M)
                *(float2*)(C + (size_t)r1 * N + c) = make_float2(acc[mt][nt][2], acc[mt][nt][3]);
        }
    }
}

// ---------- SpMM F=256, warp-per-row, fused bias (+ReLU) ----------
__global__ void k_spmm256(const float* __restrict__ sup, const float* __restrict__ bias,
                          float* __restrict__ out, int relu, int n) {
    int w = (blockIdx.x * blockDim.x + threadIdx.x) >> 5;
    int lane = threadIdx.x & 31;
    if (w >= n) return;
    int s = g_rowptr[w], e = g_rowptr[w + 1];
    float4 a0 = make_float4(0.f, 0.f, 0.f, 0.f);
    float4 a1 = a0;

    int i = s;
    for (; i + 1 < e; i += 2) {
        int2 p0 = __ldg(&g_csr[i]);
        int2 p1 = __ldg(&g_csr[i + 1]);
        float v0 = __int_as_float(p0.y);
        float v1 = __int_as_float(p1.y);
        const float4* s0 = (const float4*)(sup + (size_t)p0.x * 256);
        const float4* s1 = (const float4*)(sup + (size_t)p1.x * 256);
        float4 x0 = __ldg(&s0[lane]);
        float4 x1 = __ldg(&s0[lane + 32]);
        float4 y0 = __ldg(&s1[lane]);
        float4 y1 = __ldg(&s1[lane + 32]);
        a0.x += v0 * x0.x; a0.y += v0 * x0.y; a0.z += v0 * x0.z; a0.w += v0 * x0.w;
        a1.x += v0 * x1.x; a1.y += v0 * x1.y; a1.z += v0 * x1.z; a1.w += v0 * x1.w;
        a0.x += v1 * y0.x; a0.y += v1 * y0.y; a0.z += v1 * y0.z; a0.w += v1 * y0.w;
        a1.x += v1 * y1.x; a1.y += v1 * y1.y; a1.z += v1 * y1.z; a1.w += v1 * y1.w;
    }
    if (i < e) {
        int2 p0 = __ldg(&g_csr[i]);
        float v0 = __int_as_float(p0.y);
        const float4* s0 = (const float4*)(sup + (size_t)p0.x * 256);
        float4 x0 = __ldg(&s0[lane]);
        float4 x1 = __ldg(&s0[lane + 32]);
        a0.x += v0 * x0.x; a0.y += v0 * x0.y; a0.z += v0 * x0.z; a0.w += v0 * x0.w;
        a1.x += v0 * x1.x; a1.y += v0 * x1.y; a1.z += v0 * x1.z; a1.w += v0 * x1.w;
    }

    float4 b0 = __ldg(&((const float4*)bias)[lane]);
    float4 b1 = __ldg(&((const float4*)bias)[lane + 32]);
    a0.x += b0.x; a0.y += b0.y; a0.z += b0.z; a0.w += b0.w;
    a1.x += b1.x; a1.y += b1.y; a1.z += b1.z; a1.w += b1.w;
    if (relu) {
        a0.x = fmaxf(a0.x, 0.f); a0.y = fmaxf(a0.y, 0.f);
        a0.z = fmaxf(a0.z, 0.f); a0.w = fmaxf(a0.w, 0.f);
        a1.x = fmaxf(a1.x, 0.f); a1.y = fmaxf(a1.y, 0.f);
        a1.z = fmaxf(a1.z, 0.f); a1.w = fmaxf(a1.w, 0.f);
    }
    float4* op = (float4*)(out + (size_t)w * 256);
    op[lane] = a0;
    op[lane + 32] = a1;
}

// ---------- SpMM F=64, warp-per-row, fused bias ----------
__global__ void k_spmm64(const float* __restrict__ sup, const float* __restrict__ bias,
                         float* __restrict__ out, int n) {
    int w = (blockIdx.x * blockDim.x + threadIdx.x) >> 5;
    int lane = threadIdx.x & 31;
    if (w >= n) return;
    int s = g_rowptr[w], e = g_rowptr[w + 1];
    float2 a = make_float2(0.f, 0.f);

    int i = s;
    for (; i + 1 < e; i += 2) {
        int2 p0 = __ldg(&g_csr[i]);
        int2 p1 = __ldg(&g_csr[i + 1]);
        float v0 = __int_as_float(p0.y);
        float v1 = __int_as_float(p1.y);
        float2 x0 = __ldg(&((const float2*)(sup + (size_t)p0.x * 64))[lane]);
        float2 x1 = __ldg(&((const float2*)(sup + (size_t)p1.x * 64))[lane]);
        a.x += v0 * x0.x; a.y += v0 * x0.y;
        a.x += v1 * x1.x; a.y += v1 * x1.y;
    }
    if (i < e) {
        int2 p0 = __ldg(&g_csr[i]);
        float v0 = __int_as_float(p0.y);
        float2 x0 = __ldg(&((const float2*)(sup + (size_t)p0.x * 64))[lane]);
        a.x += v0 * x0.x; a.y += v0 * x0.y;
    }

    float2 b = __ldg(&((const float2*)bias)[lane]);
    a.x += b.x; a.y += b.y;
    ((float2*)(out + (size_t)w * 64))[lane] = a;
}

// ---------- log_softmax over 64 logits per row ----------
__global__ void k_lsm64(float* __restrict__ out, int n) {
    int w = (blockIdx.x * blockDim.x + threadIdx.x) >> 5;
    int lane = threadIdx.x & 31;
    if (w >= n) return;
    float2* p = (float2*)(out + (size_t)w * 64);
    float2 v = p[lane];
    float m = fmaxf(v.x, v.y);
    #pragma unroll
    for (int o = 16; o; o >>= 1) m = fmaxf(m, __shfl_xor_sync(0xffffffffu, m, o));
    float s = expf(v.x - m) + expf(v.y - m);
    #pragma unroll
    for (int o = 16; o; o >>= 1) s += __shfl_xor_sync(0xffffffffu, s, o);
    float l = m + logf(s);
    p[lane] = make_float2(v.x - l, v.y - l);
}

// ---------- launch ----------
extern "C" void kernel_launch(void* const* d_in, const int* in_sizes, int n_in,
                              void* d_out, int out_size) {
    const float* x    = (const float*)d_in[0];
    const int*   erow = (const int*)d_in[1];
    const int*   ecol = (const int*)d_in[2];
    const float* eval = (const float*)d_in[3];
    const float* W1   = (const float*)d_in[4];
    const float* b1   = (const float*)d_in[5];
    const float* W2   = (const float*)d_in[6];
    const float* b2   = (const float*)d_in[7];
    const float* W3   = (const float*)d_in[8];
    const float* b3   = (const float*)d_in[9];

    int N = in_sizes[0] / 512;
    int E = in_sizes[1];

    float *pA, *pB, *pW1T, *pW2T, *pW3T;
    cudaGetSymbolAddress((void**)&pA, g_A);
    cudaGetSymbolAddress((void**)&pB, g_B);
    cudaGetSymbolAddress((void**)&pW1T, g_W1T);
    cudaGetSymbolAddress((void**)&pW2T, g_W2T);
    cudaGetSymbolAddress((void**)&pW3T, g_W3T);

    // --- weight transposes (BT = [N,K], i.e. col-major B for .row.col mma) ---
    k_transpose<<<(512*256 + 255) / 256, 256>>>(W1, pW1T, 512, 256);
    k_transpose<<<(256*256 + 255) / 256, 256>>>(W2, pW2T, 256, 256);
    k_transpose<<<(256*64 + 255) / 256, 256>>>(W3, pW3T, 256, 64);

    // --- CSR build ---
    k_zero<<<(N + 255) / 256, 256>>>(N);
    k_hist<<<(E + 255) / 256, 256>>>(erow, E);
    int NB = (N + 1023) / 1024;
    k_scan1<<<NB, 1024>>>(N);
    k_scan2<<<1, 256>>>(NB);
    k_scan3<<<(N + 255) / 256, 256>>>(N);
    k_scatter<<<(E + 255) / 256, 256>>>(erow, ecol, eval, E);

    int warpBlocks = (N * 32 + 255) / 256;
    int tilesM = (N + 127) / 128;
    dim3 g256(256 / 64, tilesM);
    dim3 g64(64 / 64, tilesM);

    // layer 1: A = x@W1 ; B = relu(spmm(A) + b1)
    k_gemm_mma<<<g256, 256>>>(x, pW1T, pA, N, 512, 256);
    k_spmm256<<<warpBlocks, 256>>>(pA, b1, pB, 1, N);

    // layer 2: A = B@W2 ; B = relu(spmm(A) + b2)
    k_gemm_mma<<<g256, 256>>>(pB, pW2T, pA, N, 256, 256);
    k_spmm256<<<warpBlocks, 256>>>(pA, b2, pB, 1, N);

    // layer 3: A = B@W3 ; out = spmm(A) + b3 ; log_softmax
    k_gemm_mma<<<g64, 256>>>(pB, pW3T, pA, N, 256, 64);
    k_spmm64<<<warpBlocks, 256>>>(pA, b3, (float*)d_out, N);
    k_lsm64<<<warpBlocks, 256>>>((float*)d_out, N);
}

// round 6
// speedup vs baseline: 1.9988x; 1.2840x over previous
#include <cuda_runtime.h>
#include <cuda_bf16.h>
#include <math.h>
#include <stdint.h>

#define NMAX 100000
#define EMAX 3200000

// ---------- device scratch (allocation-free: __device__ globals) ----------
__device__ __align__(256) __nv_bfloat16 g_S16[(size_t)NMAX * 256];  // bf16 support
__device__ __align__(256) float g_B[(size_t)NMAX * 256];            // fp32 hidden
__device__ __align__(256) float g_W1T[256 * 512];
__device__ __align__(256) float g_W2T[256 * 256];
__device__ __align__(256) float g_W3T[64 * 256];
__device__ int   g_counts[NMAX];
__device__ int   g_tmp[NMAX];
__device__ int   g_rowptr[NMAX + 1];
__device__ int   g_cursor[NMAX];
__device__ int2  g_csr[EMAX];               // {col, float_as_int(val)}
__device__ int   g_bsum[256];
__device__ int   g_boff[256];

// ---------- CSR build ----------
__global__ void k_zero(int n) {
    int i = blockIdx.x * blockDim.x + threadIdx.x;
    if (i < n) g_counts[i] = 0;
}
__global__ void k_hist(const int* __restrict__ erow, int e) {
    int i = blockIdx.x * blockDim.x + threadIdx.x;
    if (i < e) atomicAdd(&g_counts[erow[i]], 1);
}
__global__ void k_scan1(int n) {
    __shared__ int sh[1024];
    int t = threadIdx.x;
    int i = blockIdx.x * 1024 + t;
    int v = (i < n) ? g_counts[i] : 0;
    sh[t] = v;
    __syncthreads();
    #pragma unroll
    for (int off = 1; off < 1024; off <<= 1) {
        int add = (t >= off) ? sh[t - off] : 0;
        __syncthreads();
        sh[t] += add;
        __syncthreads();
    }
    if (i < n) g_tmp[i] = sh[t];
    if (t == 1023) g_bsum[blockIdx.x] = sh[1023];
}
__global__ void k_scan2(int nb) {
    __shared__ int sh[256];
    int t = threadIdx.x;
    int v = (t < nb) ? g_bsum[t] : 0;
    sh[t] = v;
    __syncthreads();
    #pragma unroll
    for (int off = 1; off < 256; off <<= 1) {
        int add = (t >= off) ? sh[t - off] : 0;
        __syncthreads();
        sh[t] += add;
        __syncthreads();
    }
    if (t < nb) g_boff[t] = sh[t] - v;
}
__global__ void k_scan3(int n) {
    int i = blockIdx.x * blockDim.x + threadIdx.x;
    if (i < n) {
        int incl = g_tmp[i] + g_boff[i >> 10];
        g_rowptr[i + 1] = incl;
        g_cursor[i] = incl - g_counts[i];
        if (i == 0) g_rowptr[0] = 0;
    }
}
__global__ void k_scatter(const int* __restrict__ erow, const int* __restrict__ ecol,
                          const float* __restrict__ eval, int e) {
    int i = blockIdx.x * blockDim.x + threadIdx.x;
    if (i < e) {
        int r = erow[i];
        int pos = atomicAdd(&g_cursor[r], 1);
        g_csr[pos] = make_int2(ecol[i], __float_as_int(eval[i]));
    }
}

// ---------- small transpose: WT[n*K+k] = W[k*N+n] ----------
__global__ void k_transpose(const float* __restrict__ W, float* __restrict__ WT, int K, int N) {
    int i = blockIdx.x * blockDim.x + threadIdx.x;
    if (i < K * N) {
        int k = i / N, n = i % N;
        WT[(size_t)n * K + k] = W[i];
    }
}

// ---------- TF32 mma.sync GEMM, bf16 output: C[M,N] = A[M,K] @ BT[N,K]^T ----------
// block tile 128x64, 256 threads (8 warps as 4m x 2n), warp tile 32x32.
// Register-pipelined: prefetch chunk j+1 to regs, compute chunk j from smem,
// cvt+STS.128 to other stage, one __syncthreads per chunk.
__device__ __forceinline__ uint32_t f2tf32(float f) {
    uint32_t r;
    asm("cvt.rna.tf32.f32 %0, %1;" : "=r"(r) : "f"(f));
    return r;
}

__global__ void __launch_bounds__(256, 2)
k_gemm_mma(const float* __restrict__ A, const float* __restrict__ BT,
           __nv_bfloat16* __restrict__ C, int M, int K, int N) {
    extern __shared__ uint32_t sm[];
    // As[2][128][36], Bs[2][64][36]
    uint32_t (*As)[128][36] = (uint32_t(*)[128][36])sm;
    uint32_t (*Bs)[64][36]  = (uint32_t(*)[64][36])(sm + 2 * 128 * 36);

    int tid = threadIdx.x;
    int w = tid >> 5, lane = tid & 31;
    int gid = lane >> 2, tig = lane & 3;
    int warp_m = w >> 1, warp_n = w & 1;
    int m0w = warp_m * 32, n0w = warp_n * 32;
    int tileRow = blockIdx.y * 128;
    int tileCol = blockIdx.x * 64;

    float acc[2][4][4];
    #pragma unroll
    for (int mt = 0; mt < 2; mt++)
        #pragma unroll
        for (int nt = 0; nt < 4; nt++)
            #pragma unroll
            for (int q = 0; q < 4; q++) acc[mt][nt][q] = 0.f;

    int arow = tid >> 1;               // 0..127
    int aq0  = (tid & 1) * 4;          // 0 or 4
    int brow = tid >> 2;               // 0..63
    int bq0  = tid & 3;                // quads bq0, bq0+4

    int grA = tileRow + arow;
    const float* aptr = A + (size_t)grA * K;
    const float* bptr = BT + (size_t)(tileCol + brow) * K;
    bool aval = (grA < M);

    float4 aR[4], bR[2];

    // prefetch into regs for chunk k0
    auto LDREG = [&](int k0) {
        #pragma unroll
        for (int q = 0; q < 4; q++) {
            aR[q] = make_float4(0.f, 0.f, 0.f, 0.f);
            if (aval) aR[q] = __ldg((const float4*)(aptr + k0 + (aq0 + q) * 4));
        }
        bR[0] = __ldg((const float4*)(bptr + k0 + bq0 * 4));
        bR[1] = __ldg((const float4*)(bptr + k0 + (bq0 + 4) * 4));
    };
    // cvt + store staged regs into stage s
    auto STSMEM = [&](int s) {
        #pragma unroll
        for (int q = 0; q < 4; q++) {
            uint4 u = make_uint4(f2tf32(aR[q].x), f2tf32(aR[q].y), f2tf32(aR[q].z), f2tf32(aR[q].w));
            *(uint4*)&As[s][arow][(aq0 + q) * 4] = u;
        }
        uint4 u0 = make_uint4(f2tf32(bR[0].x), f2tf32(bR[0].y), f2tf32(bR[0].z), f2tf32(bR[0].w));
        *(uint4*)&Bs[s][brow][bq0 * 4] = u0;
        uint4 u1 = make_uint4(f2tf32(bR[1].x), f2tf32(bR[1].y), f2tf32(bR[1].z), f2tf32(bR[1].w));
        *(uint4*)&Bs[s][brow][bq0 * 4 + 16] = u1;
    };

    int NC = K / 32;
    LDREG(0);
    STSMEM(0);
    __syncthreads();

    for (int j = 0; j < NC; j++) {
        if (j + 1 < NC) LDREG((j + 1) * 32);
        int s = j & 1;
        #pragma unroll
        for (int ks = 0; ks < 4; ks++) {
            int kk = ks * 8;
            uint32_t af[2][4], bf[4][2];
            #pragma unroll
            for (int mt = 0; mt < 2; mt++) {
                int m = m0w + mt * 16 + gid;
                af[mt][0] = As[s][m][kk + tig];
                af[mt][1] = As[s][m + 8][kk + tig];
                af[mt][2] = As[s][m][kk + tig + 4];
                af[mt][3] = As[s][m + 8][kk + tig + 4];
            }
            #pragma unroll
            for (int nt = 0; nt < 4; nt++) {
                int n = n0w + nt * 8 + gid;
                bf[nt][0] = Bs[s][n][kk + tig];
                bf[nt][1] = Bs[s][n][kk + tig + 4];
            }
            #pragma unroll
            for (int mt = 0; mt < 2; mt++)
                #pragma unroll
                for (int nt = 0; nt < 4; nt++) {
                    asm volatile(
                        "mma.sync.aligned.m16n8k8.row.col.f32.tf32.tf32.f32 "
                        "{%0,%1,%2,%3}, {%4,%5,%6,%7}, {%8,%9}, {%0,%1,%2,%3};"
                        : "+f"(acc[mt][nt][0]), "+f"(acc[mt][nt][1]),
                          "+f"(acc[mt][nt][2]), "+f"(acc[mt][nt][3])
                        : "r"(af[mt][0]), "r"(af[mt][1]), "r"(af[mt][2]), "r"(af[mt][3]),
                          "r"(bf[nt][0]), "r"(bf[nt][1]));
                }
        }
        if (j + 1 < NC) {
            STSMEM((j + 1) & 1);
            __syncthreads();
        }
    }

    // epilogue: bf16x2 stores
    #pragma unroll
    for (int mt = 0; mt < 2; mt++) {
        int r0 = tileRow + m0w + mt * 16 + gid;
        int r1 = r0 + 8;
        #pragma unroll
        for (int nt = 0; nt < 4; nt++) {
            int c = tileCol + n0w + nt * 8 + tig * 2;
            if (r0 < M)
                *(__nv_bfloat162*)(C + (size_t)r0 * N + c) =
                    __float22bfloat162_rn(make_float2(acc[mt][nt][0], acc[mt][nt][1]));
            if (r1 < M)
                *(__nv_bfloat162*)(C + (size_t)r1 * N + c) =
                    __float22bfloat162_rn(make_float2(acc[mt][nt][2], acc[mt][nt][3]));
        }
    }
}

// bf16 pair -> two floats (exact)
__device__ __forceinline__ void bf2f(uint32_t u, float& lo, float& hi) {
    lo = __uint_as_float(u << 16);
    hi = __uint_as_float(u & 0xffff0000u);
}

// ---------- SpMM F=256, bf16 gather, warp-per-row, fused bias (+ReLU) ----------
__global__ void k_spmm256(const __nv_bfloat16* __restrict__ sup, const float* __restrict__ bias,
                          float* __restrict__ out, int relu, int n) {
    int w = (blockIdx.x * blockDim.x + threadIdx.x) >> 5;
    int lane = threadIdx.x & 31;
    if (w >= n) return;
    int s = g_rowptr[w], e = g_rowptr[w + 1];
    float a[8];
    #pragma unroll
    for (int q = 0; q < 8; q++) a[q] = 0.f;

    int i = s;
    for (; i + 1 < e; i += 2) {
        int2 p0 = __ldg(&g_csr[i]);
        int2 p1 = __ldg(&g_csr[i + 1]);
        float v0 = __int_as_float(p0.y);
        float v1 = __int_as_float(p1.y);
        uint4 u0 = __ldg((const uint4*)(sup + (size_t)p0.x * 256) + lane);
        uint4 u1 = __ldg((const uint4*)(sup + (size_t)p1.x * 256) + lane);
        float lo, hi;
        bf2f(u0.x, lo, hi); a[0] += v0 * lo; a[1] += v0 * hi;
        bf2f(u0.y, lo, hi); a[2] += v0 * lo; a[3] += v0 * hi;
        bf2f(u0.z, lo, hi); a[4] += v0 * lo; a[5] += v0 * hi;
        bf2f(u0.w, lo, hi); a[6] += v0 * lo; a[7] += v0 * hi;
        bf2f(u1.x, lo, hi); a[0] += v1 * lo; a[1] += v1 * hi;
        bf2f(u1.y, lo, hi); a[2] += v1 * lo; a[3] += v1 * hi;
        bf2f(u1.z, lo, hi); a[4] += v1 * lo; a[5] += v1 * hi;
        bf2f(u1.w, lo, hi); a[6] += v1 * lo; a[7] += v1 * hi;
    }
    if (i < e) {
        int2 p0 = __ldg(&g_csr[i]);
        float v0 = __int_as_float(p0.y);
        uint4 u0 = __ldg((const uint4*)(sup + (size_t)p0.x * 256) + lane);
        float lo, hi;
        bf2f(u0.x, lo, hi); a[0] += v0 * lo; a[1] += v0 * hi;
        bf2f(u0.y, lo, hi); a[2] += v0 * lo; a[3] += v0 * hi;
        bf2f(u0.z, lo, hi); a[4] += v0 * lo; a[5] += v0 * hi;
        bf2f(u0.w, lo, hi); a[6] += v0 * lo; a[7] += v0 * hi;
    }

    float4 b0 = __ldg((const float4*)bias + lane * 2);
    float4 b1 = __ldg((const float4*)bias + lane * 2 + 1);
    a[0] += b0.x; a[1] += b0.y; a[2] += b0.z; a[3] += b0.w;
    a[4] += b1.x; a[5] += b1.y; a[6] += b1.z; a[7] += b1.w;
    if (relu) {
        #pragma unroll
        for (int q = 0; q < 8; q++) a[q] = fmaxf(a[q], 0.f);
    }
    float4* op = (float4*)(out + (size_t)w * 256 + lane * 8);
    op[0] = make_float4(a[0], a[1], a[2], a[3]);
    op[1] = make_float4(a[4], a[5], a[6], a[7]);
}

// ---------- SpMM F=64, bf16 gather, warp-per-row, fused bias ----------
__global__ void k_spmm64(const __nv_bfloat16* __restrict__ sup, const float* __restrict__ bias,
                         float* __restrict__ out, int n) {
    int w = (blockIdx.x * blockDim.x + threadIdx.x) >> 5;
    int lane = threadIdx.x & 31;
    if (w >= n) return;
    int s = g_rowptr[w], e = g_rowptr[w + 1];
    float ax = 0.f, ay = 0.f;

    int i = s;
    for (; i + 1 < e; i += 2) {
        int2 p0 = __ldg(&g_csr[i]);
        int2 p1 = __ldg(&g_csr[i + 1]);
        float v0 = __int_as_float(p0.y);
        float v1 = __int_as_float(p1.y);
        uint32_t u0 = __ldg((const uint32_t*)(sup + (size_t)p0.x * 64) + lane);
        uint32_t u1 = __ldg((const uint32_t*)(sup + (size_t)p1.x * 64) + lane);
        float lo, hi;
        bf2f(u0, lo, hi); ax += v0 * lo; ay += v0 * hi;
        bf2f(u1, lo, hi); ax += v1 * lo; ay += v1 * hi;
    }
    if (i < e) {
        int2 p0 = __ldg(&g_csr[i]);
        float v0 = __int_as_float(p0.y);
        uint32_t u0 = __ldg((const uint32_t*)(sup + (size_t)p0.x * 64) + lane);
        float lo, hi;
        bf2f(u0, lo, hi); ax += v0 * lo; ay += v0 * hi;
    }

    float2 b = __ldg((const float2*)bias + lane);
    ax += b.x; ay += b.y;
    ((float2*)(out + (size_t)w * 64))[lane] = make_float2(ax, ay);
}

// ---------- log_softmax over 64 logits per row ----------
__global__ void k_lsm64(float* __restrict__ out, int n) {
    int w = (blockIdx.x * blockDim.x + threadIdx.x) >> 5;
    int lane = threadIdx.x & 31;
    if (w >= n) return;
    float2* p = (float2*)(out + (size_t)w * 64);
    float2 v = p[lane];
    float m = fmaxf(v.x, v.y);
    #pragma unroll
    for (int o = 16; o; o >>= 1) m = fmaxf(m, __shfl_xor_sync(0xffffffffu, m, o));
    float s = expf(v.x - m) + expf(v.y - m);
    #pragma unroll
    for (int o = 16; o; o >>= 1) s += __shfl_xor_sync(0xffffffffu, s, o);
    float l = m + logf(s);
    p[lane] = make_float2(v.x - l, v.y - l);
}

// ---------- launch ----------
extern "C" void kernel_launch(void* const* d_in, const int* in_sizes, int n_in,
                              void* d_out, int out_size) {
    const float* x    = (const float*)d_in[0];
    const int*   erow = (const int*)d_in[1];
    const int*   ecol = (const int*)d_in[2];
    const float* eval = (const float*)d_in[3];
    const float* W1   = (const float*)d_in[4];
    const float* b1   = (const float*)d_in[5];
    const float* W2   = (const float*)d_in[6];
    const float* b2   = (const float*)d_in[7];
    const float* W3   = (const float*)d_in[8];
    const float* b3   = (const float*)d_in[9];

    int N = in_sizes[0] / 512;
    int E = in_sizes[1];

    float *pB, *pW1T, *pW2T, *pW3T;
    __nv_bfloat16* pS;
    cudaGetSymbolAddress((void**)&pS, g_S16);
    cudaGetSymbolAddress((void**)&pB, g_B);
    cudaGetSymbolAddress((void**)&pW1T, g_W1T);
    cudaGetSymbolAddress((void**)&pW2T, g_W2T);
    cudaGetSymbolAddress((void**)&pW3T, g_W3T);

    const int SMEM = (2 * 128 * 36 + 2 * 64 * 36) * 4;   // 55296 B
    cudaFuncSetAttribute(k_gemm_mma, cudaFuncAttributeMaxDynamicSharedMemorySize, SMEM);

    // --- weight transposes (BT = [N,K], col-major B for .row.col mma) ---
    k_transpose<<<(512*256 + 255) / 256, 256>>>(W1, pW1T, 512, 256);
    k_transpose<<<(256*256 + 255) / 256, 256>>>(W2, pW2T, 256, 256);
    k_transpose<<<(256*64 + 255) / 256, 256>>>(W3, pW3T, 256, 64);

    // --- CSR build ---
    k_zero<<<(N + 255) / 256, 256>>>(N);
    k_hist<<<(E + 255) / 256, 256>>>(erow, E);
    int NB = (N + 1023) / 1024;
    k_scan1<<<NB, 1024>>>(N);
    k_scan2<<<1, 256>>>(NB);
    k_scan3<<<(N + 255) / 256, 256>>>(N);
    k_scatter<<<(E + 255) / 256, 256>>>(erow, ecol, eval, E);

    int warpBlocks = (N * 32 + 255) / 256;
    int tilesM = (N + 127) / 128;
    dim3 g256(4, tilesM);
    dim3 g64(1, tilesM);

    // layer 1: S = bf16(x@W1) ; B = relu(spmm(S) + b1)
    k_gemm_mma<<<g256, 256, SMEM>>>(x, pW1T, pS, N, 512, 256);
    k_spmm256<<<warpBlocks, 256>>>(pS, b1, pB, 1, N);

    // layer 2: S = bf16(B@W2) ; B = relu(spmm(S) + b2)
    k_gemm_mma<<<g256, 256, SMEM>>>(pB, pW2T, pS, N, 256, 256);
    k_spmm256<<<warpBlocks, 256>>>(pS, b2, pB, 1, N);

    // layer 3: S = bf16(B@W3) ; out = spmm(S) + b3 ; log_softmax
    k_gemm_mma<<<g64, 256, SMEM>>>(pB, pW3T, pS, N, 256, 64);
    k_spmm64<<<warpBlocks, 256>>>(pS, b3, (float*)d_out, N);
    k_lsm64<<<warpBlocks, 256>>>((float*)d_out, N);
}

// round 8
// speedup vs baseline: 2.3697x; 1.1856x over previous
#include <cuda_runtime.h>
#include <cuda_bf16.h>
#include <math.h>
#include <stdint.h>

#define NMAX 100000
#define EMAX 3200000

// ---------- device scratch (allocation-free: __device__ globals) ----------
__device__ __align__(256) __nv_bfloat16 g_S16[(size_t)NMAX * 256];  // bf16 support (GEMM out)
__device__ __align__(256) __nv_bfloat16 g_H16[(size_t)NMAX * 256];  // bf16 hidden (SpMM out)
__device__ __align__(256) __nv_bfloat16 g_W1T[256 * 512];
__device__ __align__(256) __nv_bfloat16 g_W2T[256 * 256];
__device__ __align__(256) __nv_bfloat16 g_W3T[64 * 256];
__device__ int   g_counts[NMAX];
__device__ int   g_tmp[NMAX];
__device__ int   g_rowptr[NMAX + 1];
__device__ int   g_cursor[NMAX];
__device__ int2  g_csr[EMAX];               // {col, float_as_int(val)}
__device__ int   g_bsum[256];
__device__ int   g_boff[256];

// ---------- CSR build ----------
__global__ void k_zero(int n) {
    int i = blockIdx.x * blockDim.x + threadIdx.x;
    if (i < n) g_counts[i] = 0;
}
__global__ void k_hist(const int* __restrict__ erow, int e) {
    int i = blockIdx.x * blockDim.x + threadIdx.x;
    if (i < e) atomicAdd(&g_counts[erow[i]], 1);
}
__global__ void k_scan1(int n) {
    __shared__ int sh[1024];
    int t = threadIdx.x;
    int i = blockIdx.x * 1024 + t;
    int v = (i < n) ? g_counts[i] : 0;
    sh[t] = v;
    __syncthreads();
    #pragma unroll
    for (int off = 1; off < 1024; off <<= 1) {
        int add = (t >= off) ? sh[t - off] : 0;
        __syncthreads();
        sh[t] += add;
        __syncthreads();
    }
    if (i < n) g_tmp[i] = sh[t];
    if (t == 1023) g_bsum[blockIdx.x] = sh[1023];
}
__global__ void k_scan2(int nb) {
    __shared__ int sh[256];
    int t = threadIdx.x;
    int v = (t < nb) ? g_bsum[t] : 0;
    sh[t] = v;
    __syncthreads();
    #pragma unroll
    for (int off = 1; off < 256; off <<= 1) {
        int add = (t >= off) ? sh[t - off] : 0;
        __syncthreads();
        sh[t] += add;
        __syncthreads();
    }
    if (t < nb) g_boff[t] = sh[t] - v;
}
__global__ void k_scan3(int n) {
    int i = blockIdx.x * blockDim.x + threadIdx.x;
    if (i < n) {
        int incl = g_tmp[i] + g_boff[i >> 10];
        g_rowptr[i + 1] = incl;
        g_cursor[i] = incl - g_counts[i];
        if (i == 0) g_rowptr[0] = 0;
    }
}
__global__ void k_scatter(const int* __restrict__ erow, const int* __restrict__ ecol,
                          const float* __restrict__ eval, int e) {
    int i = blockIdx.x * blockDim.x + threadIdx.x;
    if (i < e) {
        int r = erow[i];
        int pos = atomicAdd(&g_cursor[r], 1);
        g_csr[pos] = make_int2(ecol[i], __float_as_int(eval[i]));
    }
}

// ---------- transpose + bf16 convert: WT[n*K+k] = bf16(W[k*N+n]) ----------
__global__ void k_transpose(const float* __restrict__ W, __nv_bfloat16* __restrict__ WT,
                            int K, int N) {
    int i = blockIdx.x * blockDim.x + threadIdx.x;
    if (i < K * N) {
        int k = i / N, n = i % N;
        WT[(size_t)n * K + k] = __float2bfloat16(W[i]);
    }
}

// pack two fp32 -> bf16x2 in a u32 (round-to-nearest)
__device__ __forceinline__ uint32_t packbf(float lo, float hi) {
    uint32_t r;
    asm("cvt.rn.bf16x2.f32 %0, %1, %2;" : "=r"(r) : "f"(hi), "f"(lo));
    return r;
}

// ---------- bf16 mma.sync GEMM: C[M,N] = A[M,K] @ BT[N,K]^T ----------
// block tile 128x64, 256 threads (8 warps as 4m x 2n), warp tile 32x32,
// m16n8k16 bf16 MMA, K in chunks of 32 elements (16 u32 of bf16x2, stride 20).
// Register-pipelined: prefetch next chunk to regs while computing current.
template<int AFP32>
__global__ void __launch_bounds__(256, 2)
k_gemm_bf16(const float* __restrict__ Af, const __nv_bfloat16* __restrict__ Ah,
            const __nv_bfloat16* __restrict__ BT, __nv_bfloat16* __restrict__ C,
            int M, int K, int N) {
    __shared__ uint32_t As[2][128][20];
    __shared__ uint32_t Bs[2][64][20];

    int tid = threadIdx.x;
    int w = tid >> 5, lane = tid & 31;
    int gid = lane >> 2, tig = lane & 3;
    int warp_m = w >> 1, warp_n = w & 1;
    int m0w = warp_m * 32, n0w = warp_n * 32;
    int tileRow = blockIdx.y * 128;
    int tileCol = blockIdx.x * 64;

    float acc[2][4][4];
    #pragma unroll
    for (int mt = 0; mt < 2; mt++)
        #pragma unroll
        for (int nt = 0; nt < 4; nt++)
            #pragma unroll
            for (int q = 0; q < 4; q++) acc[mt][nt][q] = 0.f;

    int arow = tid >> 1;           // 0..127
    int ah   = (tid & 1) * 8;      // u32 offset: 0 or 8 (covers 16 bf16)
    int brow = tid >> 2;           // 0..63
    int bq   = tid & 3;            // uint4 index (8 bf16 each)

    int grA = tileRow + arow;
    bool aval = (grA < M);
    const float* aptrF = Af + (size_t)grA * K;
    const __nv_bfloat16* aptrH = Ah + (size_t)grA * K;
    const __nv_bfloat16* bptr = BT + (size_t)(tileCol + brow) * K;

    uint4 aR0, aR1, bR;

    auto LDREG = [&](int k0) {
        aR0 = make_uint4(0,0,0,0); aR1 = make_uint4(0,0,0,0);
        if (AFP32) {
            if (aval) {
                const float4* p = (const float4*)(aptrF + k0 + ah * 2);
                float4 v0 = __ldg(p), v1 = __ldg(p + 1), v2 = __ldg(p + 2), v3 = __ldg(p + 3);
                aR0 = make_uint4(packbf(v0.x, v0.y), packbf(v0.z, v0.w),
                                 packbf(v1.x, v1.y), packbf(v1.z, v1.w));
                aR1 = make_uint4(packbf(v2.x, v2.y), packbf(v2.z, v2.w),
                                 packbf(v3.x, v3.y), packbf(v3.z, v3.w));
            }
        } else {
            if (aval) {
                const uint4* p = (const uint4*)(aptrH + k0 + ah * 2);
                aR0 = __ldg(p); aR1 = __ldg(p + 1);
            }
        }
        bR = __ldg((const uint4*)(bptr + k0 + bq * 8));
    };
    auto STSMEM = [&](int s) {
        *(uint4*)&As[s][arow][ah]     = aR0;
        *(uint4*)&As[s][arow][ah + 4] = aR1;
        *(uint4*)&Bs[s][brow][bq * 4] = bR;
    };

    int NC = K / 32;
    LDREG(0);
    STSMEM(0);
    __syncthreads();

    for (int j = 0; j < NC; j++) {
        if (j + 1 < NC) LDREG((j + 1) * 32);
        int s = j & 1;
        #pragma unroll
        for (int ks = 0; ks < 2; ks++) {
            int kk = ks * 8;
            uint32_t af[2][4], bf[4][2];
            #pragma unroll
            for (int mt = 0; mt < 2; mt++) {
                int m = m0w + mt * 16 + gid;
                af[mt][0] = As[s][m][kk + tig];
                af[mt][1] = As[s][m + 8][kk + tig];
                af[mt][2] = As[s][m][kk + tig + 4];
                af[mt][3] = As[s][m + 8][kk + tig + 4];
            }
            #pragma unroll
            for (int nt = 0; nt < 4; nt++) {
                int n = n0w + nt * 8 + gid;
                bf[nt][0] = Bs[s][n][kk + tig];
                bf[nt][1] = Bs[s][n][kk + tig + 4];
            }
            #pragma unroll
            for (int mt = 0; mt < 2; mt++)
                #pragma unroll
                for (int nt = 0; nt < 4; nt++) {
                    asm volatile(
                        "mma.sync.aligned.m16n8k16.row.col.f32.bf16.bf16.f32 "
                        "{%0,%1,%2,%3}, {%4,%5,%6,%7}, {%8,%9}, {%0,%1,%2,%3};"
                        : "+f"(acc[mt][nt][0]), "+f"(acc[mt][nt][1]),
                          "+f"(acc[mt][nt][2]), "+f"(acc[mt][nt][3])
                        : "r"(af[mt][0]), "r"(af[mt][1]), "r"(af[mt][2]), "r"(af[mt][3]),
                          "r"(bf[nt][0]), "r"(bf[nt][1]));
                }
        }
        if (j + 1 < NC) {
            STSMEM((j + 1) & 1);
            __syncthreads();
        }
    }

    // epilogue: bf16x2 stores
    #pragma unroll
    for (int mt = 0; mt < 2; mt++) {
        int r0 = tileRow + m0w + mt * 16 + gid;
        int r1 = r0 + 8;
        #pragma unroll
        for (int nt = 0; nt < 4; nt++) {
            int c = tileCol + n0w + nt * 8 + tig * 2;
            if (r0 < M)
                *(uint32_t*)(C + (size_t)r0 * N + c) = packbf(acc[mt][nt][0], acc[mt][nt][1]);
            if (r1 < M)
                *(uint32_t*)(C + (size_t)r1 * N + c) = packbf(acc[mt][nt][2], acc[mt][nt][3]);
        }
    }
}

// bf16 pair -> two floats (exact)
__device__ __forceinline__ void bf2f(uint32_t u, float& lo, float& hi) {
    lo = __uint_as_float(u << 16);
    hi = __uint_as_float(u & 0xffff0000u);
}
__device__ __forceinline__ void fma8(float* a, float v, uint4 u) {
    float lo, hi;
    bf2f(u.x, lo, hi); a[0] += v * lo; a[1] += v * hi;
    bf2f(u.y, lo, hi); a[2] += v * lo; a[3] += v * hi;
    bf2f(u.z, lo, hi); a[4] += v * lo; a[5] += v * hi;
    bf2f(u.w, lo, hi); a[6] += v * lo; a[7] += v * hi;
}

// ---------- SpMM F=256, bf16 gather, warp-per-row, fused bias+ReLU, bf16 out ----------
__global__ void k_spmm256(const __nv_bfloat16* __restrict__ sup, const float* __restrict__ bias,
                          __nv_bfloat16* __restrict__ out, int n) {
    int w = (blockIdx.x * blockDim.x + threadIdx.x) >> 5;
    int lane = threadIdx.x & 31;
    if (w >= n) return;
    int s = g_rowptr[w], e = g_rowptr[w + 1];
    float a[8];
    #pragma unroll
    for (int q = 0; q < 8; q++) a[q] = 0.f;

    int i = s;
    for (; i + 3 < e; i += 4) {
        int2 p0 = __ldg(&g_csr[i]);
        int2 p1 = __ldg(&g_csr[i + 1]);
        int2 p2 = __ldg(&g_csr[i + 2]);
        int2 p3 = __ldg(&g_csr[i + 3]);
        uint4 u0 = __ldg((const uint4*)(sup + (size_t)p0.x * 256) + lane);
        uint4 u1 = __ldg((const uint4*)(sup + (size_t)p1.x * 256) + lane);
        uint4 u2 = __ldg((const uint4*)(sup + (size_t)p2.x * 256) + lane);
        uint4 u3 = __ldg((const uint4*)(sup + (size_t)p3.x * 256) + lane);
        fma8(a, __int_as_float(p0.y), u0);
        fma8(a, __int_as_float(p1.y), u1);
        fma8(a, __int_as_float(p2.y), u2);
        fma8(a, __int_as_float(p3.y), u3);
    }
    for (; i < e; i++) {
        int2 p0 = __ldg(&g_csr[i]);
        uint4 u0 = __ldg((const uint4*)(sup + (size_t)p0.x * 256) + lane);
        fma8(a, __int_as_float(p0.y), u0);
    }

    float4 b0 = __ldg((const float4*)bias + lane * 2);
    float4 b1 = __ldg((const float4*)bias + lane * 2 + 1);
    a[0] += b0.x; a[1] += b0.y; a[2] += b0.z; a[3] += b0.w;
    a[4] += b1.x; a[5] += b1.y; a[6] += b1.z; a[7] += b1.w;
    #pragma unroll
    for (int q = 0; q < 8; q++) a[q] = fmaxf(a[q], 0.f);

    uint4 o = make_uint4(packbf(a[0], a[1]), packbf(a[2], a[3]),
                         packbf(a[4], a[5]), packbf(a[6], a[7]));
    *((uint4*)(out + (size_t)w * 256) + lane) = o;
}

// ---------- SpMM F=64 + bias + fused log_softmax, fp32 out ----------
__global__ void k_spmm64_lsm(const __nv_bfloat16* __restrict__ sup, const float* __restrict__ bias,
                             float* __restrict__ out, int n) {
    int w = (blockIdx.x * blockDim.x + threadIdx.x) >> 5;
    int lane = threadIdx.x & 31;
    if (w >= n) return;
    int s = g_rowptr[w], e = g_rowptr[w + 1];
    float ax = 0.f, ay = 0.f;

    int i = s;
    for (; i + 3 < e; i += 4) {
        int2 p0 = __ldg(&g_csr[i]);
        int2 p1 = __ldg(&g_csr[i + 1]);
        int2 p2 = __ldg(&g_csr[i + 2]);
        int2 p3 = __ldg(&g_csr[i + 3]);
        uint32_t u0 = __ldg((const uint32_t*)(sup + (size_t)p0.x * 64) + lane);
        uint32_t u1 = __ldg((const uint32_t*)(sup + (size_t)p1.x * 64) + lane);
        uint32_t u2 = __ldg((const uint32_t*)(sup + (size_t)p2.x * 64) + lane);
        uint32_t u3 = __ldg((const uint32_t*)(sup + (size_t)p3.x * 64) + lane);
        float lo, hi;
        bf2f(u0, lo, hi); ax += __int_as_float(p0.y) * lo; ay += __int_as_float(p0.y) * hi;
        bf2f(u1, lo, hi); ax += __int_as_float(p1.y) * lo; ay += __int_as_float(p1.y) * hi;
        bf2f(u2, lo, hi); ax += __int_as_float(p2.y) * lo; ay += __int_as_float(p2.y) * hi;
        bf2f(u3, lo, hi); ax += __int_as_float(p3.y) * lo; ay += __int_as_float(p3.y) * hi;
    }
    for (; i < e; i++) {
        int2 p0 = __ldg(&g_csr[i]);
        uint32_t u0 = __ldg((const uint32_t*)(sup + (size_t)p0.x * 64) + lane);
        float lo, hi;
        bf2f(u0, lo, hi); ax += __int_as_float(p0.y) * lo; ay += __int_as_float(p0.y) * hi;
    }

    float2 b = __ldg((const float2*)bias + lane);
    ax += b.x; ay += b.y;

    // fused log_softmax over the warp's 64 values
    float m = fmaxf(ax, ay);
    #pragma unroll
    for (int o = 16; o; o >>= 1) m = fmaxf(m, __shfl_xor_sync(0xffffffffu, m, o));
    float sum = expf(ax - m) + expf(ay - m);
    #pragma unroll
    for (int o = 16; o; o >>= 1) sum += __shfl_xor_sync(0xffffffffu, sum, o);
    float l = m + logf(sum);
    ((float2*)(out + (size_t)w * 64))[lane] = make_float2(ax - l, ay - l);
}

// ---------- launch ----------
extern "C" void kernel_launch(void* const* d_in, const int* in_sizes, int n_in,
                              void* d_out, int out_size) {
    const float* x    = (const float*)d_in[0];
    const int*   erow = (const int*)d_in[1];
    const int*   ecol = (const int*)d_in[2];
    const float* eval = (const float*)d_in[3];
    const float* W1   = (const float*)d_in[4];
    const float* b1   = (const float*)d_in[5];
    const float* W2   = (const float*)d_in[6];
    const float* b2   = (const float*)d_in[7];
    const float* W3   = (const float*)d_in[8];
    const float* b3   = (const float*)d_in[9];

    int N = in_sizes[0] / 512;
    int E = in_sizes[1];

    __nv_bfloat16 *pS, *pH, *pW1T, *pW2T, *pW3T;
    cudaGetSymbolAddress((void**)&pS, g_S16);
    cudaGetSymbolAddress((void**)&pH, g_H16);
    cudaGetSymbolAddress((void**)&pW1T, g_W1T);
    cudaGetSymbolAddress((void**)&pW2T, g_W2T);
    cudaGetSymbolAddress((void**)&pW3T, g_W3T);

    // --- weight transposes (BT = [N,K] bf16, col-major B for .row.col mma) ---
    k_transpose<<<(512*256 + 255) / 256, 256>>>(W1, pW1T, 512, 256);
    k_transpose<<<(256*256 + 255) / 256, 256>>>(W2, pW2T, 256, 256);
    k_transpose<<<(256*64 + 255) / 256, 256>>>(W3, pW3T, 256, 64);

    // --- CSR build ---
    k_zero<<<(N + 255) / 256, 256>>>(N);
    k_hist<<<(E + 255) / 256, 256>>>(erow, E);
    int NB = (N + 1023) / 1024;
    k_scan1<<<NB, 1024>>>(N);
    k_scan2<<<1, 256>>>(NB);
    k_scan3<<<(N + 255) / 256, 256>>>(N);
    k_scatter<<<(E + 255) / 256, 256>>>(erow, ecol, eval, E);

    int warpBlocks = (N * 32 + 255) / 256;
    int tilesM = (N + 127) / 128;
    dim3 g256(4, tilesM);
    dim3 g64(1, tilesM);

    // layer 1: S = bf16(x@W1) ; H = bf16(relu(spmm(S) + b1))
    k_gemm_bf16<1><<<g256, 256>>>(x, nullptr, pW1T, pS, N, 512, 256);
    k_spmm256<<<warpBlocks, 256>>>(pS, b1, pH, N);

    // layer 2: S = bf16(H@W2) ; H = bf16(relu(spmm(S) + b2))
    k_gemm_bf16<0><<<g256, 256>>>(nullptr, pH, pW2T, pS, N, 256, 256);
    k_spmm256<<<warpBlocks, 256>>>(pS, b2, pH, N);

    // layer 3: S = bf16(H@W3) ; out = log_softmax(spmm(S) + b3)
    k_gemm_bf16<0><<<g64, 256>>>(nullptr, pH, pW3T, pS, N, 256, 64);
    k_spmm64_lsm<<<warpBlocks, 256>>>(pS, b3, (float*)d_out, N);
}

// round 9
// speedup vs baseline: 2.5287x; 1.0671x over previous
#include <cuda_runtime.h>
#include <cuda_bf16.h>
#include <cuda_fp16.h>
#include <math.h>
#include <stdint.h>

#define NMAX 100000
#define EMAX 3200000

// ---------- device scratch (allocation-free: __device__ globals) ----------
__device__ __align__(256) __nv_bfloat16 g_S16[(size_t)NMAX * 256];  // bf16 support / fp8 alias
__device__ __align__(256) __nv_bfloat16 g_H16[(size_t)NMAX * 256];  // bf16 hidden (SpMM out)
__device__ __align__(256) __nv_bfloat16 g_W1T[256 * 512];
__device__ __align__(256) __nv_bfloat16 g_W2T[256 * 256];
__device__ __align__(256) __nv_bfloat16 g_W3T[64 * 256];
__device__ int   g_counts[NMAX];
__device__ int   g_tmp[NMAX];
__device__ int   g_rowptr[NMAX + 1];
__device__ int   g_cursor[NMAX];
__device__ int2  g_csr[EMAX];               // {col, float_as_int(val)}
__device__ int   g_bsum[256];
__device__ int   g_boff[256];

// ---------- CSR build ----------
__global__ void k_hist(const int* __restrict__ erow, int e) {
    int i = blockIdx.x * blockDim.x + threadIdx.x;
    if (i < e) atomicAdd(&g_counts[erow[i]], 1);
}
__global__ void k_scan1(int n) {
    __shared__ int sh[1024];
    int t = threadIdx.x;
    int i = blockIdx.x * 1024 + t;
    int v = (i < n) ? g_counts[i] : 0;
    sh[t] = v;
    __syncthreads();
    #pragma unroll
    for (int off = 1; off < 1024; off <<= 1) {
        int add = (t >= off) ? sh[t - off] : 0;
        __syncthreads();
        sh[t] += add;
        __syncthreads();
    }
    if (i < n) g_tmp[i] = sh[t];
    if (t == 1023) g_bsum[blockIdx.x] = sh[1023];
}
__global__ void k_scan2(int nb) {
    __shared__ int sh[256];
    int t = threadIdx.x;
    int v = (t < nb) ? g_bsum[t] : 0;
    sh[t] = v;
    __syncthreads();
    #pragma unroll
    for (int off = 1; off < 256; off <<= 1) {
        int add = (t >= off) ? sh[t - off] : 0;
        __syncthreads();
        sh[t] += add;
        __syncthreads();
    }
    if (t < nb) g_boff[t] = sh[t] - v;
}
__global__ void k_scan3(int n) {
    int i = blockIdx.x * blockDim.x + threadIdx.x;
    if (i < n) {
        int incl = g_tmp[i] + g_boff[i >> 10];
        g_rowptr[i + 1] = incl;
        g_cursor[i] = incl - g_counts[i];
        if (i == 0) g_rowptr[0] = 0;
    }
}
__global__ void k_scatter(const int* __restrict__ erow, const int* __restrict__ ecol,
                          const float* __restrict__ eval, int e) {
    int i = blockIdx.x * blockDim.x + threadIdx.x;
    if (i < e) {
        int r = erow[i];
        int pos = atomicAdd(&g_cursor[r], 1);
        g_csr[pos] = make_int2(ecol[i], __float_as_int(eval[i]));
    }
}

// ---------- transpose + bf16 convert: WT[n*K+k] = bf16(W[k*N+n]) ----------
__global__ void k_transpose(const float* __restrict__ W, __nv_bfloat16* __restrict__ WT,
                            int K, int N) {
    int i = blockIdx.x * blockDim.x + threadIdx.x;
    if (i < K * N) {
        int k = i / N, n = i % N;
        WT[(size_t)n * K + k] = __float2bfloat16(W[i]);
    }
}

// ---------- pack/unpack helpers ----------
__device__ __forceinline__ uint32_t packbf(float lo, float hi) {
    uint32_t r;
    asm("cvt.rn.bf16x2.f32 %0, %1, %2;" : "=r"(r) : "f"(hi), "f"(lo));
    return r;
}
__device__ __forceinline__ uint16_t pack_e4m3x2(float lo, float hi) {
    uint16_t r;
    asm("cvt.rn.satfinite.e4m3x2.f32 %0, %1, %2;" : "=h"(r) : "f"(hi), "f"(lo));
    return r;
}
__device__ __forceinline__ void e4m3x2_to_f32(uint16_t p, float& lo, float& hi) {
    uint32_t h2;
    asm("cvt.rn.f16x2.e4m3x2 %0, %1;" : "=r"(h2) : "h"(p));
    __half2 h = *reinterpret_cast<__half2*>(&h2);
    float2 f = __half22float2(h);
    lo = f.x; hi = f.y;
}

// ---------- bf16 mma.sync GEMM: C[M,N] = A[M,K] @ BT[N,K]^T ----------
// block tile 128x64, 256 threads (8 warps as 4m x 2n), warp tile 32x32,
// m16n8k16 bf16 MMA. OUTFP8: write e4m3 (layers 1/2) else bf16 (layer 3).
template<int AFP32, int OUTFP8>
__global__ void __launch_bounds__(256, 2)
k_gemm_bf16(const float* __restrict__ Af, const __nv_bfloat16* __restrict__ Ah,
            const __nv_bfloat16* __restrict__ BT, void* __restrict__ Cv,
            int M, int K, int N) {
    __shared__ uint32_t As[2][128][20];
    __shared__ uint32_t Bs[2][64][20];

    int tid = threadIdx.x;
    int w = tid >> 5, lane = tid & 31;
    int gid = lane >> 2, tig = lane & 3;
    int warp_m = w >> 1, warp_n = w & 1;
    int m0w = warp_m * 32, n0w = warp_n * 32;
    int tileRow = blockIdx.y * 128;
    int tileCol = blockIdx.x * 64;

    float acc[2][4][4];
    #pragma unroll
    for (int mt = 0; mt < 2; mt++)
        #pragma unroll
        for (int nt = 0; nt < 4; nt++)
            #pragma unroll
            for (int q = 0; q < 4; q++) acc[mt][nt][q] = 0.f;

    int arow = tid >> 1;           // 0..127
    int ah   = (tid & 1) * 8;      // u32 offset: 0 or 8 (covers 16 bf16)
    int brow = tid >> 2;           // 0..63
    int bq   = tid & 3;            // uint4 index (8 bf16 each)

    int grA = tileRow + arow;
    bool aval = (grA < M);
    const float* aptrF = Af + (size_t)grA * K;
    const __nv_bfloat16* aptrH = Ah + (size_t)grA * K;
    const __nv_bfloat16* bptr = BT + (size_t)(tileCol + brow) * K;

    uint4 aR0, aR1, bR;

    auto LDREG = [&](int k0) {
        aR0 = make_uint4(0,0,0,0); aR1 = make_uint4(0,0,0,0);
        if (AFP32) {
            if (aval) {
                const float4* p = (const float4*)(aptrF + k0 + ah * 2);
                float4 v0 = __ldg(p), v1 = __ldg(p + 1), v2 = __ldg(p + 2), v3 = __ldg(p + 3);
                aR0 = make_uint4(packbf(v0.x, v0.y), packbf(v0.z, v0.w),
                                 packbf(v1.x, v1.y), packbf(v1.z, v1.w));
                aR1 = make_uint4(packbf(v2.x, v2.y), packbf(v2.z, v2.w),
                                 packbf(v3.x, v3.y), packbf(v3.z, v3.w));
            }
        } else {
            if (aval) {
                const uint4* p = (const uint4*)(aptrH + k0 + ah * 2);
                aR0 = __ldg(p); aR1 = __ldg(p + 1);
            }
        }
        bR = __ldg((const uint4*)(bptr + k0 + bq * 8));
    };
    auto STSMEM = [&](int s) {
        *(uint4*)&As[s][arow][ah]     = aR0;
        *(uint4*)&As[s][arow][ah + 4] = aR1;
        *(uint4*)&Bs[s][brow][bq * 4] = bR;
    };

    int NC = K / 32;
    LDREG(0);
    STSMEM(0);
    __syncthreads();

    for (int j = 0; j < NC; j++) {
        if (j + 1 < NC) LDREG((j + 1) * 32);
        int s = j & 1;
        #pragma unroll
        for (int ks = 0; ks < 2; ks++) {
            int kk = ks * 8;
            uint32_t af[2][4], bf[4][2];
            #pragma unroll
            for (int mt = 0; mt < 2; mt++) {
                int m = m0w + mt * 16 + gid;
                af[mt][0] = As[s][m][kk + tig];
                af[mt][1] = As[s][m + 8][kk + tig];
                af[mt][2] = As[s][m][kk + tig + 4];
                af[mt][3] = As[s][m + 8][kk + tig + 4];
            }
            #pragma unroll
            for (int nt = 0; nt < 4; nt++) {
                int n = n0w + nt * 8 + gid;
                bf[nt][0] = Bs[s][n][kk + tig];
                bf[nt][1] = Bs[s][n][kk + tig + 4];
            }
            #pragma unroll
            for (int mt = 0; mt < 2; mt++)
                #pragma unroll
                for (int nt = 0; nt < 4; nt++) {
                    asm volatile(
                        "mma.sync.aligned.m16n8k16.row.col.f32.bf16.bf16.f32 "
                        "{%0,%1,%2,%3}, {%4,%5,%6,%7}, {%8,%9}, {%0,%1,%2,%3};"
                        : "+f"(acc[mt][nt][0]), "+f"(acc[mt][nt][1]),
                          "+f"(acc[mt][nt][2]), "+f"(acc[mt][nt][3])
                        : "r"(af[mt][0]), "r"(af[mt][1]), "r"(af[mt][2]), "r"(af[mt][3]),
                          "r"(bf[nt][0]), "r"(bf[nt][1]));
                }
        }
        if (j + 1 < NC) {
            STSMEM((j + 1) & 1);
            __syncthreads();
        }
    }

    // epilogue
    #pragma unroll
    for (int mt = 0; mt < 2; mt++) {
        int r0 = tileRow + m0w + mt * 16 + gid;
        int r1 = r0 + 8;
        #pragma unroll
        for (int nt = 0; nt < 4; nt++) {
            int c = tileCol + n0w + nt * 8 + tig * 2;
            if (OUTFP8) {
                uint8_t* C = (uint8_t*)Cv;
                if (r0 < M)
                    *(uint16_t*)(C + (size_t)r0 * N + c) = pack_e4m3x2(acc[mt][nt][0], acc[mt][nt][1]);
                if (r1 < M)
                    *(uint16_t*)(C + (size_t)r1 * N + c) = pack_e4m3x2(acc[mt][nt][2], acc[mt][nt][3]);
            } else {
                __nv_bfloat16* C = (__nv_bfloat16*)Cv;
                if (r0 < M)
                    *(uint32_t*)(C + (size_t)r0 * N + c) = packbf(acc[mt][nt][0], acc[mt][nt][1]);
                if (r1 < M)
                    *(uint32_t*)(C + (size_t)r1 * N + c) = packbf(acc[mt][nt][2], acc[mt][nt][3]);
            }
        }
    }
}

// bf16 pair -> two floats (exact)
__device__ __forceinline__ void bf2f(uint32_t u, float& lo, float& hi) {
    lo = __uint_as_float(u << 16);
    hi = __uint_as_float(u & 0xffff0000u);
}
__device__ __forceinline__ void fma8_fp8(float* a, float v, uint2 u) {
    float lo, hi;
    e4m3x2_to_f32((uint16_t)(u.x & 0xffffu), lo, hi); a[0] += v * lo; a[1] += v * hi;
    e4m3x2_to_f32((uint16_t)(u.x >> 16),     lo, hi); a[2] += v * lo; a[3] += v * hi;
    e4m3x2_to_f32((uint16_t)(u.y & 0xffffu), lo, hi); a[4] += v * lo; a[5] += v * hi;
    e4m3x2_to_f32((uint16_t)(u.y >> 16),     lo, hi); a[6] += v * lo; a[7] += v * hi;
}

// ---------- SpMM F=256, fp8 gather, warp-per-row, fused bias+ReLU, bf16 out ----------
__global__ void k_spmm256(const uint8_t* __restrict__ sup, const float* __restrict__ bias,
                          __nv_bfloat16* __restrict__ out, int n) {
    int w = (blockIdx.x * blockDim.x + threadIdx.x) >> 5;
    int lane = threadIdx.x & 31;
    if (w >= n) return;
    int s = g_rowptr[w], e = g_rowptr[w + 1];
    float a[8];
    #pragma unroll
    for (int q = 0; q < 8; q++) a[q] = 0.f;

    int i = s;
    for (; i + 3 < e; i += 4) {
        int2 p0 = __ldg(&g_csr[i]);
        int2 p1 = __ldg(&g_csr[i + 1]);
        int2 p2 = __ldg(&g_csr[i + 2]);
        int2 p3 = __ldg(&g_csr[i + 3]);
        uint2 u0 = __ldg((const uint2*)(sup + (size_t)p0.x * 256) + lane);
        uint2 u1 = __ldg((const uint2*)(sup + (size_t)p1.x * 256) + lane);
        uint2 u2 = __ldg((const uint2*)(sup + (size_t)p2.x * 256) + lane);
        uint2 u3 = __ldg((const uint2*)(sup + (size_t)p3.x * 256) + lane);
        fma8_fp8(a, __int_as_float(p0.y), u0);
        fma8_fp8(a, __int_as_float(p1.y), u1);
        fma8_fp8(a, __int_as_float(p2.y), u2);
        fma8_fp8(a, __int_as_float(p3.y), u3);
    }
    for (; i < e; i++) {
        int2 p0 = __ldg(&g_csr[i]);
        uint2 u0 = __ldg((const uint2*)(sup + (size_t)p0.x * 256) + lane);
        fma8_fp8(a, __int_as_float(p0.y), u0);
    }

    float4 b0 = __ldg((const float4*)bias + lane * 2);
    float4 b1 = __ldg((const float4*)bias + lane * 2 + 1);
    a[0] += b0.x; a[1] += b0.y; a[2] += b0.z; a[3] += b0.w;
    a[4] += b1.x; a[5] += b1.y; a[6] += b1.z; a[7] += b1.w;
    #pragma unroll
    for (int q = 0; q < 8; q++) a[q] = fmaxf(a[q], 0.f);

    uint4 o = make_uint4(packbf(a[0], a[1]), packbf(a[2], a[3]),
                         packbf(a[4], a[5]), packbf(a[6], a[7]));
    *((uint4*)(out + (size_t)w * 256) + lane) = o;
}

// ---------- SpMM F=64 (bf16 gather) + bias + fused log_softmax, fp32 out ----------
__global__ void k_spmm64_lsm(const __nv_bfloat16* __restrict__ sup, const float* __restrict__ bias,
                             float* __restrict__ out, int n) {
    int w = (blockIdx.x * blockDim.x + threadIdx.x) >> 5;
    int lane = threadIdx.x & 31;
    if (w >= n) return;
    int s = g_rowptr[w], e = g_rowptr[w + 1];
    float ax = 0.f, ay = 0.f;

    int i = s;
    for (; i + 3 < e; i += 4) {
        int2 p0 = __ldg(&g_csr[i]);
        int2 p1 = __ldg(&g_csr[i + 1]);
        int2 p2 = __ldg(&g_csr[i + 2]);
        int2 p3 = __ldg(&g_csr[i + 3]);
        uint32_t u0 = __ldg((const uint32_t*)(sup + (size_t)p0.x * 64) + lane);
        uint32_t u1 = __ldg((const uint32_t*)(sup + (size_t)p1.x * 64) + lane);
        uint32_t u2 = __ldg((const uint32_t*)(sup + (size_t)p2.x * 64) + lane);
        uint32_t u3 = __ldg((const uint32_t*)(sup + (size_t)p3.x * 64) + lane);
        float lo, hi;
        bf2f(u0, lo, hi); ax += __int_as_float(p0.y) * lo; ay += __int_as_float(p0.y) * hi;
        bf2f(u1, lo, hi); ax += __int_as_float(p1.y) * lo; ay += __int_as_float(p1.y) * hi;
        bf2f(u2, lo, hi); ax += __int_as_float(p2.y) * lo; ay += __int_as_float(p2.y) * hi;
        bf2f(u3, lo, hi); ax += __int_as_float(p3.y) * lo; ay += __int_as_float(p3.y) * hi;
    }
    for (; i < e; i++) {
        int2 p0 = __ldg(&g_csr[i]);
        uint32_t u0 = __ldg((const uint32_t*)(sup + (size_t)p0.x * 64) + lane);
        float lo, hi;
        bf2f(u0, lo, hi); ax += __int_as_float(p0.y) * lo; ay += __int_as_float(p0.y) * hi;
    }

    float2 b = __ldg((const float2*)bias + lane);
    ax += b.x; ay += b.y;

    // fused log_softmax over the warp's 64 values
    float m = fmaxf(ax, ay);
    #pragma unroll
    for (int o = 16; o; o >>= 1) m = fmaxf(m, __shfl_xor_sync(0xffffffffu, m, o));
    float sum = expf(ax - m) + expf(ay - m);
    #pragma unroll
    for (int o = 16; o; o >>= 1) sum += __shfl_xor_sync(0xffffffffu, sum, o);
    float l = m + logf(sum);
    ((float2*)(out + (size_t)w * 64))[lane] = make_float2(ax - l, ay - l);
}

// ---------- launch ----------
extern "C" void kernel_launch(void* const* d_in, const int* in_sizes, int n_in,
                              void* d_out, int out_size) {
    const float* x    = (const float*)d_in[0];
    const int*   erow = (const int*)d_in[1];
    const int*   ecol = (const int*)d_in[2];
    const float* eval = (const float*)d_in[3];
    const float* W1   = (const float*)d_in[4];
    const float* b1   = (const float*)d_in[5];
    const float* W2   = (const float*)d_in[6];
    const float* b2   = (const float*)d_in[7];
    const float* W3   = (const float*)d_in[8];
    const float* b3   = (const float*)d_in[9];

    int N = in_sizes[0] / 512;
    int E = in_sizes[1];

    __nv_bfloat16 *pS, *pH, *pW1T, *pW2T, *pW3T;
    int* pCounts;
    cudaGetSymbolAddress((void**)&pS, g_S16);
    cudaGetSymbolAddress((void**)&pH, g_H16);
    cudaGetSymbolAddress((void**)&pW1T, g_W1T);
    cudaGetSymbolAddress((void**)&pW2T, g_W2T);
    cudaGetSymbolAddress((void**)&pW3T, g_W3T);
    cudaGetSymbolAddress((void**)&pCounts, g_counts);
    uint8_t* pS8 = (uint8_t*)pS;   // fp8 support aliases the bf16 buffer

    // --- weight transposes (BT = [N,K] bf16, col-major B for .row.col mma) ---
    k_transpose<<<(512*256 + 255) / 256, 256>>>(W1, pW1T, 512, 256);
    k_transpose<<<(256*256 + 255) / 256, 256>>>(W2, pW2T, 256, 256);
    k_transpose<<<(256*64 + 255) / 256, 256>>>(W3, pW3T, 256, 64);

    // --- CSR build ---
    cudaMemsetAsync(pCounts, 0, (size_t)N * sizeof(int));
    k_hist<<<(E + 255) / 256, 256>>>(erow, E);
    int NB = (N + 1023) / 1024;
    k_scan1<<<NB, 1024>>>(N);
    k_scan2<<<1, 256>>>(NB);
    k_scan3<<<(N + 255) / 256, 256>>>(N);
    k_scatter<<<(E + 255) / 256, 256>>>(erow, ecol, eval, E);

    int warpBlocks = (N * 32 + 255) / 256;
    int tilesM = (N + 127) / 128;
    dim3 g256(4, tilesM);
    dim3 g64(1, tilesM);

    // layer 1: S8 = fp8(x@W1) ; H = bf16(relu(spmm(S8) + b1))
    k_gemm_bf16<1, 1><<<g256, 256>>>(x, nullptr, pW1T, pS8, N, 512, 256);
    k_spmm256<<<warpBlocks, 256>>>(pS8, b1, pH, N);

    // layer 2: S8 = fp8(H@W2) ; H = bf16(relu(spmm(S8) + b2))
    k_gemm_bf16<0, 1><<<g256, 256>>>(nullptr, pH, pW2T, pS8, N, 256, 256);
    k_spmm256<<<warpBlocks, 256>>>(pS8, b2, pH, N);

    // layer 3: S = bf16(H@W3) ; out = log_softmax(spmm(S) + b3)
    k_gemm_bf16<0, 0><<<g64, 256>>>(nullptr, pH, pW3T, pS, N, 256, 64);
    k_spmm64_lsm<<<warpBlocks, 256>>>(pS, b3, (float*)d_out, N);
}